// round 13
// baseline (speedup 1.0000x reference)
#include <cuda_runtime.h>
#include <cuda_fp16.h>
#include <math.h>
#include <stdint.h>

// Problem constants
#define B_ 4
#define T_ 2048
#define D_ 1024
#define ROWS (B_ * T_)        // 8192
#define EPS 1e-5f

typedef __half fp16;

// ---------------------------------------------------------------------------
// Scratch (allocation-free: __device__ globals)
// ---------------------------------------------------------------------------
__device__ fp16 g_sc16 [(size_t)B_ * T_ * T_];  // fp16 scores
__device__ fp16 g_p    [(size_t)B_ * T_ * T_];  // fp16 probs
__device__ fp16 g_h    [ROWS * D_];             // ln1 out; reused for proj out
__device__ fp16 g_kqv  [ROWS * 3 * D_];
__device__ fp16 g_vT   [(size_t)B_ * D_ * T_];
__device__ fp16 g_at   [ROWS * D_];
__device__ fp16 g_h2   [ROWS * D_];
__device__ fp16 g_mid  [ROWS * 4 * D_];
__device__ fp16 g_WqkvT[3 * D_ * D_];
__device__ fp16 g_WprjT[D_ * D_];
__device__ fp16 g_W1T  [4 * D_ * D_];
__device__ fp16 g_W2T  [D_ * 4 * D_];

// ---------------------------------------------------------------------------
// helpers
// ---------------------------------------------------------------------------
__device__ __forceinline__ uint32_t pack2h(fp16 a, fp16 b) {
    return (uint32_t)__half_as_ushort(a) | ((uint32_t)__half_as_ushort(b) << 16);
}
__device__ __forceinline__ void mma_fp16(float* d, const uint32_t* a, const uint32_t* b) {
    asm volatile(
        "mma.sync.aligned.m16n8k16.row.col.f32.f16.f16.f32 "
        "{%0,%1,%2,%3}, {%4,%5,%6,%7}, {%8,%9}, {%0,%1,%2,%3};"
        : "+f"(d[0]), "+f"(d[1]), "+f"(d[2]), "+f"(d[3])
        : "r"(a[0]), "r"(a[1]), "r"(a[2]), "r"(a[3]),
          "r"(b[0]), "r"(b[1]));
}
__device__ __forceinline__ uint32_t smem_u32(const void* p) {
    uint32_t a;
    asm("{ .reg .u64 t; cvta.to.shared.u64 t, %1; cvt.u32.u64 %0, t; }" : "=r"(a) : "l"(p));
    return a;
}
__device__ __forceinline__ void cp16(uint32_t dst, const void* src) {
    asm volatile("cp.async.ca.shared.global [%0], [%1], 16;" :: "r"(dst), "l"(src));
}
#define CP_COMMIT() asm volatile("cp.async.commit_group;" ::: "memory")
#define CP_WAIT1()  asm volatile("cp.async.wait_group 1;" ::: "memory")
#define CP_WAIT0()  asm volatile("cp.async.wait_group 0;" ::: "memory")

#define LDSM_X4(d0, d1, d2, d3, addr) \
    asm volatile("ldmatrix.sync.aligned.m8n8.x4.shared.b16 {%0,%1,%2,%3}, [%4];" \
        : "=r"(d0), "=r"(d1), "=r"(d2), "=r"(d3) : "r"(addr))

// SMEM tile geometry: 128 rows x 32 fp16, row stride 40 elems (80B)
#define TILE_BYTES 10240
#define STAGE_BYTES (2 * TILE_BYTES)    // A + B tiles = 20480
#define NSTAGES 3
#define SMEM_BYTES (NSTAGES * STAGE_BYTES)   // 61440; x2 CTAs = 122880 fits

// ---------------------------------------------------------------------------
// 1-pass fp16 NT GEMM, 128 threads (4 warps of 64x64), 3-stage cp.async,
// 1 sync per chunk, 2 CTAs/SM.
// C[M,N] = alpha*(A @ B^T) (+bias)
// EPI: 0=fp32 out, 2=fp16 out, 3=gelu+fp16 out
// CMODE: 0=dense, 1=causal block skip, 2=causal K clip (by reversed)
// ---------------------------------------------------------------------------
template <int EPI, int CMODE>
__global__ void __launch_bounds__(128, 2) gemm_h(
    const fp16* __restrict__ A, const fp16* __restrict__ Bm,
    const float* __restrict__ bias,
    float* __restrict__ Cf, fp16* __restrict__ Ch,
    int K, int lda, int ldb, int ldc,
    long long sA, long long sB, long long sC, float alpha)
{
    const int bx = blockIdx.x, bz = blockIdx.z;
    const int by = (CMODE == 2) ? (gridDim.y - 1 - blockIdx.y) : blockIdx.y;
    if (CMODE == 1 && bx > by) return;

    extern __shared__ fp16 smem[];
    const uint32_t sb = smem_u32(smem);

    A  += sA * bz;
    Bm += sB * bz;

    const int m0 = by * 128, n0 = bx * 128;
    int Kend = K;
    if (CMODE == 2) { int ke = (by + 1) * 128; if (ke < K) Kend = ke; }
    const int NC = Kend >> 5;

    const int tid = threadIdx.x;
    const int wid = tid >> 5, lane = tid & 31;
    const int wm = wid & 1, wn = wid >> 1;      // warp grid 2(m) x 2(n), 64x64 each
    const int g = lane >> 2, tig = lane & 3;

    const uint32_t a_loff = (uint32_t)(wm * 64 * 80) +
        (uint32_t)(((lane & 7) + ((lane >> 3) & 1) * 8) * 80 + ((lane >> 4) & 1) * 16);
    const uint32_t b_loff = (uint32_t)(wn * 64 * 80) +
        (uint32_t)(((lane & 7) + ((lane >> 4) & 1) * 8) * 80 + ((lane >> 3) & 1) * 16);

    // loader: thread t owns A row t and B row t (4 x 16B chunks each)
    const fp16* pA = A  + (size_t)(m0 + tid) * lda;
    const fp16* pB = Bm + (size_t)(n0 + tid) * ldb;
    const uint32_t dbase = sb + tid * 80;

    auto issue = [&](int kc, int buf) {
        const uint32_t d0 = dbase + buf * STAGE_BYTES;
        const int ko = kc * 32;
        #pragma unroll
        for (int c = 0; c < 4; c++) {
            cp16(d0 + c * 16,              pA + ko + c * 8);
            cp16(d0 + TILE_BYTES + c * 16, pB + ko + c * 8);
        }
    };

    float acc[4][8][4];
    #pragma unroll
    for (int i = 0; i < 4; i++)
        #pragma unroll
        for (int j = 0; j < 8; j++)
            #pragma unroll
            for (int r = 0; r < 4; r++) acc[i][j][r] = 0.f;

    issue(0, 0); CP_COMMIT();
    issue(1, 1); CP_COMMIT();

    int buf = 0;
    for (int kc = 0; kc < NC; kc++) {
        if (kc + 1 < NC) { CP_WAIT1(); } else { CP_WAIT0(); }
        __syncthreads();

        const uint32_t stage = sb + buf * STAGE_BYTES;
        const uint32_t aT = stage + a_loff;
        const uint32_t bT = stage + TILE_BYTES + b_loff;

        #pragma unroll
        for (int kk2 = 0; kk2 < 64; kk2 += 32) {
            uint32_t af[4][4], bf[8][2];
            #pragma unroll
            for (int mt = 0; mt < 4; mt++)
                LDSM_X4(af[mt][0], af[mt][1], af[mt][2], af[mt][3], aT + mt * 1280 + kk2);
            #pragma unroll
            for (int p = 0; p < 4; p++)
                LDSM_X4(bf[2*p][0], bf[2*p][1], bf[2*p+1][0], bf[2*p+1][1], bT + p * 1280 + kk2);
            #pragma unroll
            for (int mt = 0; mt < 4; mt++)
                #pragma unroll
                for (int nt = 0; nt < 8; nt++)
                    mma_fp16(acc[mt][nt], af[mt], bf[nt]);
        }

        if (kc + 2 < NC) {
            issue(kc + 2, (buf + 2) % NSTAGES);
            CP_COMMIT();
        }
        buf = (buf + 1) % NSTAGES;
    }

    // epilogue
    if (EPI == 0) Cf += sC * bz;
    else Ch += sC * bz;

    #pragma unroll
    for (int mt = 0; mt < 4; mt++) {
        #pragma unroll
        for (int nt = 0; nt < 8; nt++) {
            int m = m0 + wm * 64 + mt * 16 + g;
            int n = n0 + wn * 64 + nt * 8 + tig * 2;
            float2 bv = make_float2(0.f, 0.f);
            if (bias) bv = __ldg((const float2*)(bias + n));
            #pragma unroll
            for (int half_ = 0; half_ < 2; half_++) {
                float vx = acc[mt][nt][half_ * 2 + 0] * alpha + bv.x;
                float vy = acc[mt][nt][half_ * 2 + 1] * alpha + bv.y;
                if (EPI == 3) {
                    const float c0 = 0.7978845608028654f, c1 = 0.044715f;
                    vx = 0.5f * vx * (1.f + tanhf(c0 * (vx + c1 * vx * vx * vx)));
                    vy = 0.5f * vy * (1.f + tanhf(c0 * (vy + c1 * vy * vy * vy)));
                }
                size_t off = (size_t)(m + half_ * 8) * ldc + n;
                if (EPI == 0) {
                    *(float2*)(Cf + off) = make_float2(vx, vy);
                } else {
                    *(uint32_t*)(Ch + off) = pack2h(__float2half_rn(vx), __float2half_rn(vy));
                }
            }
        }
    }
}

// ---------------------------------------------------------------------------
// Weight transpose -> fp16
// ---------------------------------------------------------------------------
__global__ void __launch_bounds__(256) transpose_h_f32(
    const float* __restrict__ in, fp16* __restrict__ out, int ldi, int ldo)
{
    __shared__ float t[32][33];
    const int c0 = blockIdx.x * 32, r0 = blockIdx.y * 32;
    const int x = threadIdx.x, y = threadIdx.y;
    #pragma unroll
    for (int i = 0; i < 4; i++)
        t[y + i * 8][x] = in[(size_t)(r0 + y + i * 8) * ldi + c0 + x];
    __syncthreads();
    #pragma unroll
    for (int i = 0; i < 4; i++)
        out[(size_t)(c0 + y + i * 8) * ldo + r0 + x] = __float2half_rn(t[x][y + i * 8]);
}

// ---------------------------------------------------------------------------
// fp16 transpose (V -> V^T), batched
// ---------------------------------------------------------------------------
__global__ void __launch_bounds__(256) transpose_h(
    const fp16* __restrict__ in, fp16* __restrict__ out,
    int ldi, int ldo, long long sI, long long sO)
{
    __shared__ fp16 t[32][33];
    in  += sI * blockIdx.z;
    out += sO * blockIdx.z;
    const int c0 = blockIdx.x * 32, r0 = blockIdx.y * 32;
    const int x = threadIdx.x, y = threadIdx.y;
    #pragma unroll
    for (int i = 0; i < 4; i++)
        t[y + i * 8][x] = in[(size_t)(r0 + y + i * 8) * ldi + c0 + x];
    __syncthreads();
    #pragma unroll
    for (int i = 0; i < 4; i++)
        out[(size_t)(c0 + y + i * 8) * ldo + r0 + x] = t[x][y + i * 8];
}

// ---------------------------------------------------------------------------
// LayerNorm -> fp16 out. FIN=0: fp32 input, FIN=1: fp16 input.
// ---------------------------------------------------------------------------
template <int FIN>
__global__ void __launch_bounds__(256) ln_half(
    const void* __restrict__ xin, const float* __restrict__ gamma,
    const float* __restrict__ beta, fp16* __restrict__ o)
{
    __shared__ float4 xc[D_ / 4];
    const int row = blockIdx.x;

    float s = 0.f, ss = 0.f;
    {
        float4 v;
        if (FIN == 0) {
            v = __ldg((const float4*)xin + (size_t)row * (D_ / 4) + threadIdx.x);
        } else {
            uint2 pk = __ldg((const uint2*)xin + (size_t)row * (D_ / 4) + threadIdx.x);
            v.x = __half2float(__ushort_as_half((unsigned short)(pk.x & 0xFFFF)));
            v.y = __half2float(__ushort_as_half((unsigned short)(pk.x >> 16)));
            v.z = __half2float(__ushort_as_half((unsigned short)(pk.y & 0xFFFF)));
            v.w = __half2float(__ushort_as_half((unsigned short)(pk.y >> 16)));
        }
        xc[threadIdx.x] = v;
        s  = v.x + v.y + v.z + v.w;
        ss = v.x * v.x + v.y * v.y + v.z * v.z + v.w * v.w;
    }
    __shared__ float rs[8], rss[8];
    #pragma unroll
    for (int o2 = 16; o2 > 0; o2 >>= 1) {
        s  += __shfl_down_sync(0xffffffffu, s,  o2);
        ss += __shfl_down_sync(0xffffffffu, ss, o2);
    }
    int wid = threadIdx.x >> 5, lid = threadIdx.x & 31;
    if (lid == 0) { rs[wid] = s; rss[wid] = ss; }
    __syncthreads();
    __shared__ float s_mu, s_rstd;
    if (threadIdx.x == 0) {
        float ts = 0.f, tss = 0.f;
        #pragma unroll
        for (int i = 0; i < 8; i++) { ts += rs[i]; tss += rss[i]; }
        float mu = ts / D_;
        float var = tss / D_ - mu * mu;
        s_mu = mu;
        s_rstd = rsqrtf(var + EPS);
    }
    __syncthreads();
    float mu = s_mu, rstd = s_rstd;
    {
        int i = threadIdx.x;
        float4 v = xc[i];
        float4 gm = __ldg((const float4*)gamma + i);
        float4 bt = __ldg((const float4*)beta + i);
        fp16 h0 = __float2half_rn((v.x - mu) * rstd * gm.x + bt.x);
        fp16 h1 = __float2half_rn((v.y - mu) * rstd * gm.y + bt.y);
        fp16 h2 = __float2half_rn((v.z - mu) * rstd * gm.z + bt.z);
        fp16 h3 = __float2half_rn((v.w - mu) * rstd * gm.w + bt.w);
        uint2 pk = make_uint2(pack2h(h0, h1), pack2h(h2, h3));
        *(uint2*)(o + (size_t)row * D_ + i * 4) = pk;
    }
}

// ---------------------------------------------------------------------------
// Causal softmax: fp16 scores -> fp16 probs (fast exp, fill to block edge)
// ---------------------------------------------------------------------------
__global__ void __launch_bounds__(256) softmax_h(
    const fp16* __restrict__ sc, fp16* __restrict__ pr)
{
    __shared__ float cache[T_];
    const int t = blockIdx.x, b = blockIdx.y;
    const size_t ro = ((size_t)b * T_ + t) * T_;
    const fp16* row = sc + ro;
    const int n = t + 1;
    const int blk_end = ((t >> 7) + 1) << 7;

    __shared__ float red[8];
    __shared__ float s_bc;

    float mx = -INFINITY;
    for (int i = threadIdx.x; i < n; i += 256) {
        float v = __half2float(row[i]);
        cache[i] = v;
        mx = fmaxf(mx, v);
    }
    #pragma unroll
    for (int o = 16; o > 0; o >>= 1) mx = fmaxf(mx, __shfl_down_sync(0xffffffffu, mx, o));
    int wid = threadIdx.x >> 5, lid = threadIdx.x & 31;
    if (lid == 0) red[wid] = mx;
    __syncthreads();
    if (threadIdx.x == 0) {
        float m = red[0];
        #pragma unroll
        for (int i = 1; i < 8; i++) m = fmaxf(m, red[i]);
        s_bc = m;
    }
    __syncthreads();
    mx = s_bc;

    float sum = 0.f;
    for (int i = threadIdx.x; i < n; i += 256) {
        float e = __expf(cache[i] - mx);
        cache[i] = e;
        sum += e;
    }
    #pragma unroll
    for (int o = 16; o > 0; o >>= 1) sum += __shfl_down_sync(0xffffffffu, sum, o);
    if (lid == 0) red[wid] = sum;
    __syncthreads();
    if (threadIdx.x == 0) {
        float tot = 0.f;
        #pragma unroll
        for (int i = 0; i < 8; i++) tot += red[i];
        s_bc = 1.f / tot;
    }
    __syncthreads();
    float inv = s_bc;
    for (int i = threadIdx.x; i < n; i += 256)
        pr[ro + i] = __float2half_rn(cache[i] * inv);
    const fp16 z = __float2half(0.f);
    for (int i = n + threadIdx.x; i < blk_end; i += 256)
        pr[ro + i] = z;
}

// ---------------------------------------------------------------------------
// launch
// ---------------------------------------------------------------------------
extern "C" void kernel_launch(void* const* d_in, const int* in_sizes, int n_in,
                              void* d_out, int out_size)
{
    const float* x     = (const float*)d_in[0];
    const float* ln1_g = (const float*)d_in[1];
    const float* ln1_b = (const float*)d_in[2];
    const float* Wqkv  = (const float*)d_in[3];
    const float* bqkv  = (const float*)d_in[4];
    const float* Wproj = (const float*)d_in[5];
    const float* bproj = (const float*)d_in[6];
    const float* ln2_g = (const float*)d_in[7];
    const float* ln2_b = (const float*)d_in[8];
    const float* W1    = (const float*)d_in[9];
    const float* b1    = (const float*)d_in[10];
    const float* W2    = (const float*)d_in[11];
    const float* b2    = (const float*)d_in[12];
    float* out = (float*)d_out;

    fp16 *p_sc16, *p_p, *p_h, *p_kqv, *p_vT, *p_at, *p_h2, *p_mid;
    fp16 *WqT, *WpT, *W1T, *W2T;

    cudaGetSymbolAddress((void**)&p_sc16, g_sc16);
    cudaGetSymbolAddress((void**)&p_p,    g_p);
    cudaGetSymbolAddress((void**)&p_h,    g_h);
    cudaGetSymbolAddress((void**)&p_kqv,  g_kqv);
    cudaGetSymbolAddress((void**)&p_vT,   g_vT);
    cudaGetSymbolAddress((void**)&p_at,   g_at);
    cudaGetSymbolAddress((void**)&p_h2,   g_h2);
    cudaGetSymbolAddress((void**)&p_mid,  g_mid);
    cudaGetSymbolAddress((void**)&WqT,    g_WqkvT);
    cudaGetSymbolAddress((void**)&WpT,    g_WprjT);
    cudaGetSymbolAddress((void**)&W1T,    g_W1T);
    cudaGetSymbolAddress((void**)&W2T,    g_W2T);

    cudaFuncSetAttribute((const void*)gemm_h<2, 0>, cudaFuncAttributeMaxDynamicSharedMemorySize, SMEM_BYTES);
    cudaFuncSetAttribute((const void*)gemm_h<0, 0>, cudaFuncAttributeMaxDynamicSharedMemorySize, SMEM_BYTES);
    cudaFuncSetAttribute((const void*)gemm_h<3, 0>, cudaFuncAttributeMaxDynamicSharedMemorySize, SMEM_BYTES);
    cudaFuncSetAttribute((const void*)gemm_h<2, 1>, cudaFuncAttributeMaxDynamicSharedMemorySize, SMEM_BYTES);
    cudaFuncSetAttribute((const void*)gemm_h<2, 2>, cudaFuncAttributeMaxDynamicSharedMemorySize, SMEM_BYTES);

    const float inv_sqrt_T = 1.0f / sqrtf((float)T_);
    dim3 tb(32, 8);

    // Weight transpose -> fp16 (once)
    transpose_h_f32<<<dim3(3 * D_ / 32, D_ / 32), tb>>>(Wqkv,  WqT, 3 * D_, D_);
    transpose_h_f32<<<dim3(D_ / 32,     D_ / 32), tb>>>(Wproj, WpT, D_,     D_);
    transpose_h_f32<<<dim3(4 * D_ / 32, D_ / 32), tb>>>(W1,    W1T, 4 * D_, D_);
    transpose_h_f32<<<dim3(D_ / 32, 4 * D_ / 32), tb>>>(W2,    W2T, D_, 4 * D_);

    // 1. LN1 (fp32 in) -> fp16 h
    ln_half<0><<<ROWS, 256>>>(x, ln1_g, ln1_b, p_h);

    // 2. QKV GEMM -> fp16 kqv
    gemm_h<2, 0><<<dim3(3 * D_ / 128, ROWS / 128, 1), 128, SMEM_BYTES>>>(
        p_h, WqT, bqkv, nullptr, p_kqv,
        D_, D_, D_, 3 * D_, 0, 0, 0, 1.f);

    // 3. V^T, batched
    transpose_h<<<dim3(D_ / 32, T_ / 32, B_), tb>>>(
        p_kqv + 2 * D_, p_vT, 3 * D_, T_,
        (long long)T_ * 3 * D_, (long long)D_ * T_);

    // 4. scores = q @ k^T * inv_sqrt_T (lower-tri blocks) -> fp16
    gemm_h<2, 1><<<dim3(T_ / 128, T_ / 128, B_), 128, SMEM_BYTES>>>(
        p_kqv + D_, p_kqv, nullptr, nullptr, p_sc16,
        D_, 3 * D_, 3 * D_, T_,
        (long long)T_ * 3 * D_, (long long)T_ * 3 * D_, (long long)T_ * T_, inv_sqrt_T);

    // 5. softmax -> fp16 probs
    softmax_h<<<dim3(T_, B_), 256>>>(p_sc16, p_p);

    // 6. attn @ v (K clipped, heavy CTAs first) -> fp16 at
    gemm_h<2, 2><<<dim3(D_ / 128, T_ / 128, B_), 128, SMEM_BYTES>>>(
        p_p, p_vT, nullptr, nullptr, p_at,
        T_, T_, T_, D_,
        (long long)T_ * T_, (long long)D_ * T_, (long long)T_ * D_, 1.f);

    // 7. proj -> fp16 (reuse g_h, free after QKV)
    gemm_h<2, 0><<<dim3(D_ / 128, ROWS / 128, 1), 128, SMEM_BYTES>>>(
        p_at, WpT, bproj, nullptr, p_h,
        D_, D_, D_, D_, 0, 0, 0, 1.f);

    // 8. LN2 (fp16 in) -> fp16 h2
    ln_half<1><<<ROWS, 256>>>(p_h, ln2_g, ln2_b, p_h2);

    // 9. MLP up + GELU -> fp16 mid
    gemm_h<3, 0><<<dim3(4 * D_ / 128, ROWS / 128, 1), 128, SMEM_BYTES>>>(
        p_h2, W1T, b1, nullptr, p_mid,
        D_, D_, D_, 4 * D_, 0, 0, 0, 1.f);

    // 10. MLP down -> fp32 out
    gemm_h<0, 0><<<dim3(D_ / 128, ROWS / 128, 1), 128, SMEM_BYTES>>>(
        p_mid, W2T, b2, out, nullptr,
        4 * D_, 4 * D_, 4 * D_, D_, 0, 0, 0, 1.f);
}

// round 14
// speedup vs baseline: 1.3093x; 1.3093x over previous
#include <cuda_runtime.h>
#include <cuda_fp16.h>
#include <math.h>
#include <stdint.h>

// Problem constants
#define B_ 4
#define T_ 2048
#define D_ 1024
#define ROWS (B_ * T_)        // 8192
#define EPS 1e-5f

typedef __half fp16;

// ---------------------------------------------------------------------------
// Scratch (allocation-free: __device__ globals)
// ---------------------------------------------------------------------------
__device__ fp16 g_sc16 [(size_t)B_ * T_ * T_];  // fp16 scores
__device__ fp16 g_p    [(size_t)B_ * T_ * T_];  // fp16 probs
__device__ fp16 g_h    [ROWS * D_];             // ln1 out; reused for proj out
__device__ fp16 g_kqv  [ROWS * 3 * D_];
__device__ fp16 g_vT   [(size_t)B_ * D_ * T_];
__device__ fp16 g_at   [ROWS * D_];
__device__ fp16 g_h2   [ROWS * D_];
__device__ fp16 g_mid  [ROWS * 4 * D_];
__device__ fp16 g_WqkvT[3 * D_ * D_];
__device__ fp16 g_WprjT[D_ * D_];
__device__ fp16 g_W1T  [4 * D_ * D_];
__device__ fp16 g_W2T  [D_ * 4 * D_];

// ---------------------------------------------------------------------------
// helpers
// ---------------------------------------------------------------------------
__device__ __forceinline__ uint32_t pack2h(fp16 a, fp16 b) {
    return (uint32_t)__half_as_ushort(a) | ((uint32_t)__half_as_ushort(b) << 16);
}
__device__ __forceinline__ void mma_fp16(float* d, const uint32_t* a, const uint32_t* b) {
    asm volatile(
        "mma.sync.aligned.m16n8k16.row.col.f32.f16.f16.f32 "
        "{%0,%1,%2,%3}, {%4,%5,%6,%7}, {%8,%9}, {%0,%1,%2,%3};"
        : "+f"(d[0]), "+f"(d[1]), "+f"(d[2]), "+f"(d[3])
        : "r"(a[0]), "r"(a[1]), "r"(a[2]), "r"(a[3]),
          "r"(b[0]), "r"(b[1]));
}
__device__ __forceinline__ uint32_t smem_u32(const void* p) {
    uint32_t a;
    asm("{ .reg .u64 t; cvta.to.shared.u64 t, %1; cvt.u32.u64 %0, t; }" : "=r"(a) : "l"(p));
    return a;
}
__device__ __forceinline__ void cp16(uint32_t dst, const void* src) {
    asm volatile("cp.async.cg.shared.global [%0], [%1], 16;" :: "r"(dst), "l"(src));
}
#define CP_COMMIT() asm volatile("cp.async.commit_group;" ::: "memory")
#define CP_WAIT2()  asm volatile("cp.async.wait_group 2;" ::: "memory")
#define CP_WAIT1()  asm volatile("cp.async.wait_group 1;" ::: "memory")
#define CP_WAIT0()  asm volatile("cp.async.wait_group 0;" ::: "memory")

#define LDSM_X4(d0, d1, d2, d3, addr) \
    asm volatile("ldmatrix.sync.aligned.m8n8.x4.shared.b16 {%0,%1,%2,%3}, [%4];" \
        : "=r"(d0), "=r"(d1), "=r"(d2), "=r"(d3) : "r"(addr))

// SMEM tile geometry: 128 rows x 32 fp16, row stride 40 elems (80B)
#define TILE_BYTES 10240
#define STAGE_BYTES (2 * TILE_BYTES)    // A + B tiles = 20480
#define NSTAGES 4
#define SMEM_BYTES (NSTAGES * STAGE_BYTES)   // 81920; x2 CTAs = 163840 <= 227KB

// ---------------------------------------------------------------------------
// 1-pass fp16 NT GEMM, 256 threads (8 warps of 64x32), 4-stage cp.async,
// 1 sync per chunk, 2 CTAs/SM (16 warps/SM).
// C[M,N] = alpha*(A @ B^T) (+bias)
// EPI: 0=fp32 out, 2=fp16 out, 3=gelu+fp16 out
// CMODE: 0=dense, 1=causal block skip, 2=causal K clip (by reversed)
// ---------------------------------------------------------------------------
template <int EPI, int CMODE>
__global__ void __launch_bounds__(256, 2) gemm_h(
    const fp16* __restrict__ A, const fp16* __restrict__ Bm,
    const float* __restrict__ bias,
    float* __restrict__ Cf, fp16* __restrict__ Ch,
    int K, int lda, int ldb, int ldc,
    long long sA, long long sB, long long sC, float alpha)
{
    const int bx = blockIdx.x, bz = blockIdx.z;
    const int by = (CMODE == 2) ? (gridDim.y - 1 - blockIdx.y) : blockIdx.y;
    if (CMODE == 1 && bx > by) return;

    extern __shared__ fp16 smem[];
    const uint32_t sb = smem_u32(smem);

    A  += sA * bz;
    Bm += sB * bz;

    const int m0 = by * 128, n0 = bx * 128;
    int Kend = K;
    if (CMODE == 2) { int ke = (by + 1) * 128; if (ke < K) Kend = ke; }
    const int NC = Kend >> 5;

    const int tid = threadIdx.x;
    const int wid = tid >> 5, lane = tid & 31;
    const int wm = wid & 1, wn = wid >> 1;      // warp grid 2(m) x 4(n), 64x32
    const int g = lane >> 2, tig = lane & 3;

    const uint32_t a_loff = (uint32_t)(((lane & 7) + ((lane >> 3) & 1) * 8) * 80 + ((lane >> 4) & 1) * 16);
    const uint32_t b_loff = (uint32_t)(((lane & 7) + ((lane >> 4) & 1) * 8) * 80 + ((lane >> 3) & 1) * 16);

    const int lrow = tid >> 1;
    const int lc   = (tid & 1) * 2;

    const fp16* pA = A  + (size_t)(m0 + lrow) * lda + lc * 8;
    const fp16* pB = Bm + (size_t)(n0 + lrow) * ldb + lc * 8;
    const uint32_t dbase = sb + lrow * 80 + lc * 16;

    auto issue = [&](int kc, int buf) {
        const uint32_t d0 = dbase + buf * STAGE_BYTES;
        const int ko = kc * 32;
        cp16(d0,                   pA + ko);
        cp16(d0 + 16,              pA + ko + 8);
        cp16(d0 + TILE_BYTES,      pB + ko);
        cp16(d0 + TILE_BYTES + 16, pB + ko + 8);
    };

    float acc[4][4][4];
    #pragma unroll
    for (int i = 0; i < 4; i++)
        #pragma unroll
        for (int j = 0; j < 4; j++)
            #pragma unroll
            for (int r = 0; r < 4; r++) acc[i][j][r] = 0.f;

    // prime up to 3 stages
    issue(0, 0); CP_COMMIT();
    if (NC > 1) { issue(1, 1); CP_COMMIT(); }
    if (NC > 2) { issue(2, 2); CP_COMMIT(); }

    int buf = 0;
    for (int kc = 0; kc < NC; kc++) {
        // ensure group for chunk kc is complete
        if (kc + 3 <= NC - 1)      { CP_WAIT2(); }
        else if (kc + 2 <= NC - 1) { CP_WAIT1(); }
        else                       { CP_WAIT0(); }
        __syncthreads();

        const uint32_t stage = sb + buf * STAGE_BYTES;
        const uint32_t aT = stage + (uint32_t)(wm * 64 * 80) + a_loff;
        const uint32_t bT = stage + TILE_BYTES + (uint32_t)(wn * 32 * 80) + b_loff;

        #pragma unroll
        for (int kk2 = 0; kk2 < 64; kk2 += 32) {
            uint32_t af[4][4], bf[4][2];
            #pragma unroll
            for (int mt = 0; mt < 4; mt++)
                LDSM_X4(af[mt][0], af[mt][1], af[mt][2], af[mt][3], aT + mt * 1280 + kk2);
            #pragma unroll
            for (int p = 0; p < 2; p++)
                LDSM_X4(bf[2*p][0], bf[2*p][1], bf[2*p+1][0], bf[2*p+1][1], bT + p * 1280 + kk2);
            #pragma unroll
            for (int mt = 0; mt < 4; mt++)
                #pragma unroll
                for (int nt = 0; nt < 4; nt++)
                    mma_fp16(acc[mt][nt], af[mt], bf[nt]);
        }

        // prefetch chunk kc+3 into the buffer consumed at kc-1 (sync above makes safe)
        if (kc + 3 < NC) {
            issue(kc + 3, (buf + 3) % NSTAGES);
            CP_COMMIT();
        }
        buf = (buf + 1) % NSTAGES;
    }

    // epilogue
    if (EPI == 0) Cf += sC * bz;
    else Ch += sC * bz;

    #pragma unroll
    for (int mt = 0; mt < 4; mt++) {
        #pragma unroll
        for (int nt = 0; nt < 4; nt++) {
            int m = m0 + wm * 64 + mt * 16 + g;
            int n = n0 + wn * 32 + nt * 8 + tig * 2;
            float2 bv = make_float2(0.f, 0.f);
            if (bias) bv = __ldg((const float2*)(bias + n));
            #pragma unroll
            for (int half_ = 0; half_ < 2; half_++) {
                float vx = acc[mt][nt][half_ * 2 + 0] * alpha + bv.x;
                float vy = acc[mt][nt][half_ * 2 + 1] * alpha + bv.y;
                if (EPI == 3) {
                    const float c0 = 0.7978845608028654f, c1 = 0.044715f;
                    vx = 0.5f * vx * (1.f + tanhf(c0 * (vx + c1 * vx * vx * vx)));
                    vy = 0.5f * vy * (1.f + tanhf(c0 * (vy + c1 * vy * vy * vy)));
                }
                size_t off = (size_t)(m + half_ * 8) * ldc + n;
                if (EPI == 0) {
                    *(float2*)(Cf + off) = make_float2(vx, vy);
                } else {
                    *(uint32_t*)(Ch + off) = pack2h(__float2half_rn(vx), __float2half_rn(vy));
                }
            }
        }
    }
}

// ---------------------------------------------------------------------------
// Weight transpose -> fp16
// ---------------------------------------------------------------------------
__global__ void __launch_bounds__(256) transpose_h_f32(
    const float* __restrict__ in, fp16* __restrict__ out, int ldi, int ldo)
{
    __shared__ float t[32][33];
    const int c0 = blockIdx.x * 32, r0 = blockIdx.y * 32;
    const int x = threadIdx.x, y = threadIdx.y;
    #pragma unroll
    for (int i = 0; i < 4; i++)
        t[y + i * 8][x] = in[(size_t)(r0 + y + i * 8) * ldi + c0 + x];
    __syncthreads();
    #pragma unroll
    for (int i = 0; i < 4; i++)
        out[(size_t)(c0 + y + i * 8) * ldo + r0 + x] = __float2half_rn(t[x][y + i * 8]);
}

// ---------------------------------------------------------------------------
// fp16 transpose (V -> V^T), batched
// ---------------------------------------------------------------------------
__global__ void __launch_bounds__(256) transpose_h(
    const fp16* __restrict__ in, fp16* __restrict__ out,
    int ldi, int ldo, long long sI, long long sO)
{
    __shared__ fp16 t[32][33];
    in  += sI * blockIdx.z;
    out += sO * blockIdx.z;
    const int c0 = blockIdx.x * 32, r0 = blockIdx.y * 32;
    const int x = threadIdx.x, y = threadIdx.y;
    #pragma unroll
    for (int i = 0; i < 4; i++)
        t[y + i * 8][x] = in[(size_t)(r0 + y + i * 8) * ldi + c0 + x];
    __syncthreads();
    #pragma unroll
    for (int i = 0; i < 4; i++)
        out[(size_t)(c0 + y + i * 8) * ldo + r0 + x] = t[x][y + i * 8];
}

// ---------------------------------------------------------------------------
// LayerNorm -> fp16 out. FIN=0: fp32 input, FIN=1: fp16 input.
// ---------------------------------------------------------------------------
template <int FIN>
__global__ void __launch_bounds__(256) ln_half(
    const void* __restrict__ xin, const float* __restrict__ gamma,
    const float* __restrict__ beta, fp16* __restrict__ o)
{
    __shared__ float4 xc[D_ / 4];
    const int row = blockIdx.x;

    float s = 0.f, ss = 0.f;
    {
        float4 v;
        if (FIN == 0) {
            v = __ldg((const float4*)xin + (size_t)row * (D_ / 4) + threadIdx.x);
        } else {
            uint2 pk = __ldg((const uint2*)xin + (size_t)row * (D_ / 4) + threadIdx.x);
            v.x = __half2float(__ushort_as_half((unsigned short)(pk.x & 0xFFFF)));
            v.y = __half2float(__ushort_as_half((unsigned short)(pk.x >> 16)));
            v.z = __half2float(__ushort_as_half((unsigned short)(pk.y & 0xFFFF)));
            v.w = __half2float(__ushort_as_half((unsigned short)(pk.y >> 16)));
        }
        xc[threadIdx.x] = v;
        s  = v.x + v.y + v.z + v.w;
        ss = v.x * v.x + v.y * v.y + v.z * v.z + v.w * v.w;
    }
    __shared__ float rs[8], rss[8];
    #pragma unroll
    for (int o2 = 16; o2 > 0; o2 >>= 1) {
        s  += __shfl_down_sync(0xffffffffu, s,  o2);
        ss += __shfl_down_sync(0xffffffffu, ss, o2);
    }
    int wid = threadIdx.x >> 5, lid = threadIdx.x & 31;
    if (lid == 0) { rs[wid] = s; rss[wid] = ss; }
    __syncthreads();
    __shared__ float s_mu, s_rstd;
    if (threadIdx.x == 0) {
        float ts = 0.f, tss = 0.f;
        #pragma unroll
        for (int i = 0; i < 8; i++) { ts += rs[i]; tss += rss[i]; }
        float mu = ts / D_;
        float var = tss / D_ - mu * mu;
        s_mu = mu;
        s_rstd = rsqrtf(var + EPS);
    }
    __syncthreads();
    float mu = s_mu, rstd = s_rstd;
    {
        int i = threadIdx.x;
        float4 v = xc[i];
        float4 gm = __ldg((const float4*)gamma + i);
        float4 bt = __ldg((const float4*)beta + i);
        fp16 h0 = __float2half_rn((v.x - mu) * rstd * gm.x + bt.x);
        fp16 h1 = __float2half_rn((v.y - mu) * rstd * gm.y + bt.y);
        fp16 h2 = __float2half_rn((v.z - mu) * rstd * gm.z + bt.z);
        fp16 h3 = __float2half_rn((v.w - mu) * rstd * gm.w + bt.w);
        uint2 pk = make_uint2(pack2h(h0, h1), pack2h(h2, h3));
        *(uint2*)(o + (size_t)row * D_ + i * 4) = pk;
    }
}

// ---------------------------------------------------------------------------
// Causal softmax: fp16 scores -> fp16 probs (fast exp, fill to block edge)
// ---------------------------------------------------------------------------
__global__ void __launch_bounds__(256) softmax_h(
    const fp16* __restrict__ sc, fp16* __restrict__ pr)
{
    __shared__ float cache[T_];
    const int t = blockIdx.x, b = blockIdx.y;
    const size_t ro = ((size_t)b * T_ + t) * T_;
    const fp16* row = sc + ro;
    const int n = t + 1;
    const int blk_end = ((t >> 7) + 1) << 7;

    __shared__ float red[8];
    __shared__ float s_bc;

    float mx = -INFINITY;
    for (int i = threadIdx.x; i < n; i += 256) {
        float v = __half2float(row[i]);
        cache[i] = v;
        mx = fmaxf(mx, v);
    }
    #pragma unroll
    for (int o = 16; o > 0; o >>= 1) mx = fmaxf(mx, __shfl_down_sync(0xffffffffu, mx, o));
    int wid = threadIdx.x >> 5, lid = threadIdx.x & 31;
    if (lid == 0) red[wid] = mx;
    __syncthreads();
    if (threadIdx.x == 0) {
        float m = red[0];
        #pragma unroll
        for (int i = 1; i < 8; i++) m = fmaxf(m, red[i]);
        s_bc = m;
    }
    __syncthreads();
    mx = s_bc;

    float sum = 0.f;
    for (int i = threadIdx.x; i < n; i += 256) {
        float e = __expf(cache[i] - mx);
        cache[i] = e;
        sum += e;
    }
    #pragma unroll
    for (int o = 16; o > 0; o >>= 1) sum += __shfl_down_sync(0xffffffffu, sum, o);
    if (lid == 0) red[wid] = sum;
    __syncthreads();
    if (threadIdx.x == 0) {
        float tot = 0.f;
        #pragma unroll
        for (int i = 0; i < 8; i++) tot += red[i];
        s_bc = 1.f / tot;
    }
    __syncthreads();
    float inv = s_bc;
    for (int i = threadIdx.x; i < n; i += 256)
        pr[ro + i] = __float2half_rn(cache[i] * inv);
    const fp16 z = __float2half(0.f);
    for (int i = n + threadIdx.x; i < blk_end; i += 256)
        pr[ro + i] = z;
}

// ---------------------------------------------------------------------------
// launch
// ---------------------------------------------------------------------------
extern "C" void kernel_launch(void* const* d_in, const int* in_sizes, int n_in,
                              void* d_out, int out_size)
{
    const float* x     = (const float*)d_in[0];
    const float* ln1_g = (const float*)d_in[1];
    const float* ln1_b = (const float*)d_in[2];
    const float* Wqkv  = (const float*)d_in[3];
    const float* bqkv  = (const float*)d_in[4];
    const float* Wproj = (const float*)d_in[5];
    const float* bproj = (const float*)d_in[6];
    const float* ln2_g = (const float*)d_in[7];
    const float* ln2_b = (const float*)d_in[8];
    const float* W1    = (const float*)d_in[9];
    const float* b1    = (const float*)d_in[10];
    const float* W2    = (const float*)d_in[11];
    const float* b2    = (const float*)d_in[12];
    float* out = (float*)d_out;

    fp16 *p_sc16, *p_p, *p_h, *p_kqv, *p_vT, *p_at, *p_h2, *p_mid;
    fp16 *WqT, *WpT, *W1T, *W2T;

    cudaGetSymbolAddress((void**)&p_sc16, g_sc16);
    cudaGetSymbolAddress((void**)&p_p,    g_p);
    cudaGetSymbolAddress((void**)&p_h,    g_h);
    cudaGetSymbolAddress((void**)&p_kqv,  g_kqv);
    cudaGetSymbolAddress((void**)&p_vT,   g_vT);
    cudaGetSymbolAddress((void**)&p_at,   g_at);
    cudaGetSymbolAddress((void**)&p_h2,   g_h2);
    cudaGetSymbolAddress((void**)&p_mid,  g_mid);
    cudaGetSymbolAddress((void**)&WqT,    g_WqkvT);
    cudaGetSymbolAddress((void**)&WpT,    g_WprjT);
    cudaGetSymbolAddress((void**)&W1T,    g_W1T);
    cudaGetSymbolAddress((void**)&W2T,    g_W2T);

    cudaFuncSetAttribute((const void*)gemm_h<2, 0>, cudaFuncAttributeMaxDynamicSharedMemorySize, SMEM_BYTES);
    cudaFuncSetAttribute((const void*)gemm_h<0, 0>, cudaFuncAttributeMaxDynamicSharedMemorySize, SMEM_BYTES);
    cudaFuncSetAttribute((const void*)gemm_h<3, 0>, cudaFuncAttributeMaxDynamicSharedMemorySize, SMEM_BYTES);
    cudaFuncSetAttribute((const void*)gemm_h<2, 1>, cudaFuncAttributeMaxDynamicSharedMemorySize, SMEM_BYTES);
    cudaFuncSetAttribute((const void*)gemm_h<2, 2>, cudaFuncAttributeMaxDynamicSharedMemorySize, SMEM_BYTES);

    const float inv_sqrt_T = 1.0f / sqrtf((float)T_);
    dim3 tb(32, 8);

    // Weight transpose -> fp16 (once)
    transpose_h_f32<<<dim3(3 * D_ / 32, D_ / 32), tb>>>(Wqkv,  WqT, 3 * D_, D_);
    transpose_h_f32<<<dim3(D_ / 32,     D_ / 32), tb>>>(Wproj, WpT, D_,     D_);
    transpose_h_f32<<<dim3(4 * D_ / 32, D_ / 32), tb>>>(W1,    W1T, 4 * D_, D_);
    transpose_h_f32<<<dim3(D_ / 32, 4 * D_ / 32), tb>>>(W2,    W2T, D_, 4 * D_);

    // 1. LN1 (fp32 in) -> fp16 h
    ln_half<0><<<ROWS, 256>>>(x, ln1_g, ln1_b, p_h);

    // 2. QKV GEMM -> fp16 kqv
    gemm_h<2, 0><<<dim3(3 * D_ / 128, ROWS / 128, 1), 256, SMEM_BYTES>>>(
        p_h, WqT, bqkv, nullptr, p_kqv,
        D_, D_, D_, 3 * D_, 0, 0, 0, 1.f);

    // 3. V^T, batched
    transpose_h<<<dim3(D_ / 32, T_ / 32, B_), tb>>>(
        p_kqv + 2 * D_, p_vT, 3 * D_, T_,
        (long long)T_ * 3 * D_, (long long)D_ * T_);

    // 4. scores = q @ k^T * inv_sqrt_T (lower-tri blocks) -> fp16
    gemm_h<2, 1><<<dim3(T_ / 128, T_ / 128, B_), 256, SMEM_BYTES>>>(
        p_kqv + D_, p_kqv, nullptr, nullptr, p_sc16,
        D_, 3 * D_, 3 * D_, T_,
        (long long)T_ * 3 * D_, (long long)T_ * 3 * D_, (long long)T_ * T_, inv_sqrt_T);

    // 5. softmax -> fp16 probs
    softmax_h<<<dim3(T_, B_), 256>>>(p_sc16, p_p);

    // 6. attn @ v (K clipped, heavy CTAs first) -> fp16 at
    gemm_h<2, 2><<<dim3(D_ / 128, T_ / 128, B_), 256, SMEM_BYTES>>>(
        p_p, p_vT, nullptr, nullptr, p_at,
        T_, T_, T_, D_,
        (long long)T_ * T_, (long long)D_ * T_, (long long)T_ * D_, 1.f);

    // 7. proj -> fp16 (reuse g_h)
    gemm_h<2, 0><<<dim3(D_ / 128, ROWS / 128, 1), 256, SMEM_BYTES>>>(
        p_at, WpT, bproj, nullptr, p_h,
        D_, D_, D_, D_, 0, 0, 0, 1.f);

    // 8. LN2 (fp16 in) -> fp16 h2
    ln_half<1><<<ROWS, 256>>>(p_h, ln2_g, ln2_b, p_h2);

    // 9. MLP up + GELU -> fp16 mid
    gemm_h<3, 0><<<dim3(4 * D_ / 128, ROWS / 128, 1), 256, SMEM_BYTES>>>(
        p_h2, W1T, b1, nullptr, p_mid,
        D_, D_, D_, 4 * D_, 0, 0, 0, 1.f);

    // 10. MLP down -> fp32 out
    gemm_h<0, 0><<<dim3(D_ / 128, ROWS / 128, 1), 256, SMEM_BYTES>>>(
        p_mid, W2T, b2, out, nullptr,
        4 * D_, 4 * D_, 4 * D_, D_, 0, 0, 0, 1.f);
}

// round 16
// speedup vs baseline: 1.3151x; 1.0044x over previous
#include <cuda_runtime.h>
#include <cuda_fp16.h>
#include <math.h>
#include <stdint.h>

// Problem constants
#define B_ 4
#define T_ 2048
#define D_ 1024
#define ROWS (B_ * T_)        // 8192
#define EPS 1e-5f

typedef __half fp16;

// ---------------------------------------------------------------------------
// Scratch (allocation-free: __device__ globals)
// ---------------------------------------------------------------------------
__device__ fp16 g_sc16 [(size_t)B_ * T_ * T_];  // fp16 scores
__device__ fp16 g_p    [(size_t)B_ * T_ * T_];  // fp16 probs
__device__ fp16 g_h    [ROWS * D_];             // ln1 out; reused for proj out
__device__ fp16 g_kqv  [ROWS * 3 * D_];
__device__ fp16 g_vT   [(size_t)B_ * D_ * T_];
__device__ fp16 g_at   [ROWS * D_];
__device__ fp16 g_h2   [ROWS * D_];
__device__ fp16 g_mid  [ROWS * 4 * D_];
__device__ fp16 g_WqkvT[3 * D_ * D_];
__device__ fp16 g_WprjT[D_ * D_];
__device__ fp16 g_W1T  [4 * D_ * D_];
__device__ fp16 g_W2T  [D_ * 4 * D_];

// ---------------------------------------------------------------------------
// helpers
// ---------------------------------------------------------------------------
__device__ __forceinline__ uint32_t pack2h(fp16 a, fp16 b) {
    return (uint32_t)__half_as_ushort(a) | ((uint32_t)__half_as_ushort(b) << 16);
}
__device__ __forceinline__ void mma_fp16(float* d, const uint32_t* a, const uint32_t* b) {
    asm volatile(
        "mma.sync.aligned.m16n8k16.row.col.f32.f16.f16.f32 "
        "{%0,%1,%2,%3}, {%4,%5,%6,%7}, {%8,%9}, {%0,%1,%2,%3};"
        : "+f"(d[0]), "+f"(d[1]), "+f"(d[2]), "+f"(d[3])
        : "r"(a[0]), "r"(a[1]), "r"(a[2]), "r"(a[3]),
          "r"(b[0]), "r"(b[1]));
}
__device__ __forceinline__ uint32_t smem_u32(const void* p) {
    uint32_t a;
    asm("{ .reg .u64 t; cvta.to.shared.u64 t, %1; cvt.u32.u64 %0, t; }" : "=r"(a) : "l"(p));
    return a;
}
__device__ __forceinline__ void cp16(uint32_t dst, const void* src) {
    asm volatile("cp.async.cg.shared.global [%0], [%1], 16;" :: "r"(dst), "l"(src));
}
#define CP_COMMIT() asm volatile("cp.async.commit_group;" ::: "memory")
#define CP_WAIT2()  asm volatile("cp.async.wait_group 2;" ::: "memory")
#define CP_WAIT1()  asm volatile("cp.async.wait_group 1;" ::: "memory")
#define CP_WAIT0()  asm volatile("cp.async.wait_group 0;" ::: "memory")

#define LDSM_X4(d0, d1, d2, d3, addr) \
    asm volatile("ldmatrix.sync.aligned.m8n8.x4.shared.b16 {%0,%1,%2,%3}, [%4];" \
        : "=r"(d0), "=r"(d1), "=r"(d2), "=r"(d3) : "r"(addr))

// SMEM tile geometry: 128 rows x 32 fp16, row stride 40 elems (80B)
#define TILE_BYTES 10240
#define STAGE_BYTES (2 * TILE_BYTES)    // A + B tiles = 20480
#define NSTAGES 4
#define SMEM_BYTES (NSTAGES * STAGE_BYTES)   // 81920; x2 CTAs = 163840 <= 227KB

// ---------------------------------------------------------------------------
// 1-pass fp16 NT GEMM, 256 threads (8 warps of 64x32), 4-stage cp.async,
// 1 sync per chunk, 2 CTAs/SM (16 warps/SM).  [verified race-free: prefetch
// target (buf+3)%4 is never in use by any warp]
// C[M,N] = alpha*(A @ B^T) (+bias)
// EPI: 0=fp32 out, 2=fp16 out, 3=gelu+fp16 out
// CMODE: 0=dense, 1=causal block skip, 2=causal K clip (by reversed)
// ---------------------------------------------------------------------------
template <int EPI, int CMODE>
__global__ void __launch_bounds__(256, 2) gemm_h(
    const fp16* __restrict__ A, const fp16* __restrict__ Bm,
    const float* __restrict__ bias,
    float* __restrict__ Cf, fp16* __restrict__ Ch,
    int K, int lda, int ldb, int ldc,
    long long sA, long long sB, long long sC, float alpha)
{
    const int bx = blockIdx.x, bz = blockIdx.z;
    const int by = (CMODE == 2) ? (gridDim.y - 1 - blockIdx.y) : blockIdx.y;
    if (CMODE == 1 && bx > by) return;

    extern __shared__ fp16 smem[];
    const uint32_t sb = smem_u32(smem);

    A  += sA * bz;
    Bm += sB * bz;

    const int m0 = by * 128, n0 = bx * 128;
    int Kend = K;
    if (CMODE == 2) { int ke = (by + 1) * 128; if (ke < K) Kend = ke; }
    const int NC = Kend >> 5;

    const int tid = threadIdx.x;
    const int wid = tid >> 5, lane = tid & 31;
    const int wm = wid & 1, wn = wid >> 1;      // warp grid 2(m) x 4(n), 64x32
    const int g = lane >> 2, tig = lane & 3;

    const uint32_t a_loff = (uint32_t)(((lane & 7) + ((lane >> 3) & 1) * 8) * 80 + ((lane >> 4) & 1) * 16);
    const uint32_t b_loff = (uint32_t)(((lane & 7) + ((lane >> 4) & 1) * 8) * 80 + ((lane >> 3) & 1) * 16);

    const int lrow = tid >> 1;
    const int lc   = (tid & 1) * 2;

    const fp16* pA = A  + (size_t)(m0 + lrow) * lda + lc * 8;
    const fp16* pB = Bm + (size_t)(n0 + lrow) * ldb + lc * 8;
    const uint32_t dbase = sb + lrow * 80 + lc * 16;

    auto issue = [&](int kc, int buf) {
        const uint32_t d0 = dbase + buf * STAGE_BYTES;
        const int ko = kc * 32;
        cp16(d0,                   pA + ko);
        cp16(d0 + 16,              pA + ko + 8);
        cp16(d0 + TILE_BYTES,      pB + ko);
        cp16(d0 + TILE_BYTES + 16, pB + ko + 8);
    };

    float acc[4][4][4];
    #pragma unroll
    for (int i = 0; i < 4; i++)
        #pragma unroll
        for (int j = 0; j < 4; j++)
            #pragma unroll
            for (int r = 0; r < 4; r++) acc[i][j][r] = 0.f;

    // prime up to 3 stages
    issue(0, 0); CP_COMMIT();
    if (NC > 1) { issue(1, 1); CP_COMMIT(); }
    if (NC > 2) { issue(2, 2); CP_COMMIT(); }

    int buf = 0;
    for (int kc = 0; kc < NC; kc++) {
        // ensure group for chunk kc is complete
        if (kc + 3 <= NC - 1)      { CP_WAIT2(); }
        else if (kc + 2 <= NC - 1) { CP_WAIT1(); }
        else                       { CP_WAIT0(); }
        __syncthreads();

        const uint32_t stage = sb + buf * STAGE_BYTES;
        const uint32_t aT = stage + (uint32_t)(wm * 64 * 80) + a_loff;
        const uint32_t bT = stage + TILE_BYTES + (uint32_t)(wn * 32 * 80) + b_loff;

        #pragma unroll
        for (int kk2 = 0; kk2 < 64; kk2 += 32) {
            uint32_t af[4][4], bf[4][2];
            #pragma unroll
            for (int mt = 0; mt < 4; mt++)
                LDSM_X4(af[mt][0], af[mt][1], af[mt][2], af[mt][3], aT + mt * 1280 + kk2);
            #pragma unroll
            for (int p = 0; p < 2; p++)
                LDSM_X4(bf[2*p][0], bf[2*p][1], bf[2*p+1][0], bf[2*p+1][1], bT + p * 1280 + kk2);
            #pragma unroll
            for (int mt = 0; mt < 4; mt++)
                #pragma unroll
                for (int nt = 0; nt < 4; nt++)
                    mma_fp16(acc[mt][nt], af[mt], bf[nt]);
        }

        // prefetch chunk kc+3 into an idle buffer (sync above makes safe)
        if (kc + 3 < NC) {
            issue(kc + 3, (buf + 3) % NSTAGES);
            CP_COMMIT();
        }
        buf = (buf + 1) % NSTAGES;
    }

    // epilogue
    if (EPI == 0) Cf += sC * bz;
    else Ch += sC * bz;

    #pragma unroll
    for (int mt = 0; mt < 4; mt++) {
        #pragma unroll
        for (int nt = 0; nt < 4; nt++) {
            int m = m0 + wm * 64 + mt * 16 + g;
            int n = n0 + wn * 32 + nt * 8 + tig * 2;
            float2 bv = make_float2(0.f, 0.f);
            if (bias) bv = __ldg((const float2*)(bias + n));
            #pragma unroll
            for (int half_ = 0; half_ < 2; half_++) {
                float vx = acc[mt][nt][half_ * 2 + 0] * alpha + bv.x;
                float vy = acc[mt][nt][half_ * 2 + 1] * alpha + bv.y;
                if (EPI == 3) {
                    const float c0 = 0.7978845608028654f, c1 = 0.044715f;
                    vx = 0.5f * vx * (1.f + tanhf(c0 * (vx + c1 * vx * vx * vx)));
                    vy = 0.5f * vy * (1.f + tanhf(c0 * (vy + c1 * vy * vy * vy)));
                }
                size_t off = (size_t)(m + half_ * 8) * ldc + n;
                if (EPI == 0) {
                    *(float2*)(Cf + off) = make_float2(vx, vy);
                } else {
                    *(uint32_t*)(Ch + off) = pack2h(__float2half_rn(vx), __float2half_rn(vy));
                }
            }
        }
    }
}

// ---------------------------------------------------------------------------
// All 4 weight transposes in ONE launch: 1D grid over 32x32 tiles
//   0      .. 3071   : Wqkv  [1024 x 3072] -> WqkvT  (96 x-tiles, 32 y-tiles)
//   3072   .. 4095   : Wproj [1024 x 1024]           (32, 32)
//   4096   .. 8191   : W1    [1024 x 4096]           (128, 32)
//   8192   .. 12287  : W2    [4096 x 1024]           (32, 128)
// ---------------------------------------------------------------------------
__global__ void __launch_bounds__(256) transpose_all(
    const float* __restrict__ Wqkv, const float* __restrict__ Wproj,
    const float* __restrict__ W1, const float* __restrict__ W2,
    fp16* __restrict__ WqT, fp16* __restrict__ WpT,
    fp16* __restrict__ W1T, fp16* __restrict__ W2T)
{
    int t = blockIdx.x;
    const float* in; fp16* out;
    int ldi, ldo, bx, by;
    if (t < 3072)      { in = Wqkv;  out = WqT; ldi = 3072; ldo = 1024; t -= 0;    bx = t % 96;  by = t / 96;  }
    else if (t < 4096) { in = Wproj; out = WpT; ldi = 1024; ldo = 1024; t -= 3072; bx = t % 32;  by = t / 32;  }
    else if (t < 8192) { in = W1;    out = W1T; ldi = 4096; ldo = 1024; t -= 4096; bx = t % 128; by = t / 128; }
    else               { in = W2;    out = W2T; ldi = 1024; ldo = 4096; t -= 8192; bx = t % 32;  by = t / 32;  }

    __shared__ float tl[32][33];
    const int c0 = bx * 32, r0 = by * 32;
    const int x = threadIdx.x & 31, y = threadIdx.x >> 5;
    #pragma unroll
    for (int i = 0; i < 4; i++)
        tl[y + i * 8][x] = in[(size_t)(r0 + y + i * 8) * ldi + c0 + x];
    __syncthreads();
    #pragma unroll
    for (int i = 0; i < 4; i++)
        out[(size_t)(c0 + y + i * 8) * ldo + r0 + x] = __float2half_rn(tl[x][y + i * 8]);
}

// ---------------------------------------------------------------------------
// fp16 transpose (V -> V^T), batched
// ---------------------------------------------------------------------------
__global__ void __launch_bounds__(256) transpose_h(
    const fp16* __restrict__ in, fp16* __restrict__ out,
    int ldi, int ldo, long long sI, long long sO)
{
    __shared__ fp16 t[32][33];
    in  += sI * blockIdx.z;
    out += sO * blockIdx.z;
    const int c0 = blockIdx.x * 32, r0 = blockIdx.y * 32;
    const int x = threadIdx.x, y = threadIdx.y;
    #pragma unroll
    for (int i = 0; i < 4; i++)
        t[y + i * 8][x] = in[(size_t)(r0 + y + i * 8) * ldi + c0 + x];
    __syncthreads();
    #pragma unroll
    for (int i = 0; i < 4; i++)
        out[(size_t)(c0 + y + i * 8) * ldo + r0 + x] = t[x][y + i * 8];
}

// ---------------------------------------------------------------------------
// LayerNorm -> fp16 out. FIN=0: fp32 input, FIN=1: fp16 input.
// ---------------------------------------------------------------------------
template <int FIN>
__global__ void __launch_bounds__(256) ln_half(
    const void* __restrict__ xin, const float* __restrict__ gamma,
    const float* __restrict__ beta, fp16* __restrict__ o)
{
    __shared__ float4 xc[D_ / 4];
    const int row = blockIdx.x;

    float s = 0.f, ss = 0.f;
    {
        float4 v;
        if (FIN == 0) {
            v = __ldg((const float4*)xin + (size_t)row * (D_ / 4) + threadIdx.x);
        } else {
            uint2 pk = __ldg((const uint2*)xin + (size_t)row * (D_ / 4) + threadIdx.x);
            v.x = __half2float(__ushort_as_half((unsigned short)(pk.x & 0xFFFF)));
            v.y = __half2float(__ushort_as_half((unsigned short)(pk.x >> 16)));
            v.z = __half2float(__ushort_as_half((unsigned short)(pk.y & 0xFFFF)));
            v.w = __half2float(__ushort_as_half((unsigned short)(pk.y >> 16)));
        }
        xc[threadIdx.x] = v;
        s  = v.x + v.y + v.z + v.w;
        ss = v.x * v.x + v.y * v.y + v.z * v.z + v.w * v.w;
    }
    __shared__ float rs[8], rss[8];
    #pragma unroll
    for (int o2 = 16; o2 > 0; o2 >>= 1) {
        s  += __shfl_down_sync(0xffffffffu, s,  o2);
        ss += __shfl_down_sync(0xffffffffu, ss, o2);
    }
    int wid = threadIdx.x >> 5, lid = threadIdx.x & 31;
    if (lid == 0) { rs[wid] = s; rss[wid] = ss; }
    __syncthreads();
    __shared__ float s_mu, s_rstd;
    if (threadIdx.x == 0) {
        float ts = 0.f, tss = 0.f;
        #pragma unroll
        for (int i = 0; i < 8; i++) { ts += rs[i]; tss += rss[i]; }
        float mu = ts / D_;
        float var = tss / D_ - mu * mu;
        s_mu = mu;
        s_rstd = rsqrtf(var + EPS);
    }
    __syncthreads();
    float mu = s_mu, rstd = s_rstd;
    {
        int i = threadIdx.x;
        float4 v = xc[i];
        float4 gm = __ldg((const float4*)gamma + i);
        float4 bt = __ldg((const float4*)beta + i);
        fp16 h0 = __float2half_rn((v.x - mu) * rstd * gm.x + bt.x);
        fp16 h1 = __float2half_rn((v.y - mu) * rstd * gm.y + bt.y);
        fp16 h2 = __float2half_rn((v.z - mu) * rstd * gm.z + bt.z);
        fp16 h3 = __float2half_rn((v.w - mu) * rstd * gm.w + bt.w);
        uint2 pk = make_uint2(pack2h(h0, h1), pack2h(h2, h3));
        *(uint2*)(o + (size_t)row * D_ + i * 4) = pk;
    }
}

// ---------------------------------------------------------------------------
// Causal softmax: fp16 scores -> fp16 probs (fast exp, fill to block edge)
// ---------------------------------------------------------------------------
__global__ void __launch_bounds__(256) softmax_h(
    const fp16* __restrict__ sc, fp16* __restrict__ pr)
{
    __shared__ float cache[T_];
    const int t = blockIdx.x, b = blockIdx.y;
    const size_t ro = ((size_t)b * T_ + t) * T_;
    const fp16* row = sc + ro;
    const int n = t + 1;
    const int blk_end = ((t >> 7) + 1) << 7;

    __shared__ float red[8];
    __shared__ float s_bc;

    float mx = -INFINITY;
    for (int i = threadIdx.x; i < n; i += 256) {
        float v = __half2float(row[i]);
        cache[i] = v;
        mx = fmaxf(mx, v);
    }
    #pragma unroll
    for (int o = 16; o > 0; o >>= 1) mx = fmaxf(mx, __shfl_down_sync(0xffffffffu, mx, o));
    int wid = threadIdx.x >> 5, lid = threadIdx.x & 31;
    if (lid == 0) red[wid] = mx;
    __syncthreads();
    if (threadIdx.x == 0) {
        float m = red[0];
        #pragma unroll
        for (int i = 1; i < 8; i++) m = fmaxf(m, red[i]);
        s_bc = m;
    }
    __syncthreads();
    mx = s_bc;

    float sum = 0.f;
    for (int i = threadIdx.x; i < n; i += 256) {
        float e = __expf(cache[i] - mx);
        cache[i] = e;
        sum += e;
    }
    #pragma unroll
    for (int o = 16; o > 0; o >>= 1) sum += __shfl_down_sync(0xffffffffu, sum, o);
    if (lid == 0) red[wid] = sum;
    __syncthreads();
    if (threadIdx.x == 0) {
        float tot = 0.f;
        #pragma unroll
        for (int i = 0; i < 8; i++) tot += red[i];
        s_bc = 1.f / tot;
    }
    __syncthreads();
    float inv = s_bc;
    for (int i = threadIdx.x; i < n; i += 256)
        pr[ro + i] = __float2half_rn(cache[i] * inv);
    const fp16 z = __float2half(0.f);
    for (int i = n + threadIdx.x; i < blk_end; i += 256)
        pr[ro + i] = z;
}

// ---------------------------------------------------------------------------
// launch
// ---------------------------------------------------------------------------
extern "C" void kernel_launch(void* const* d_in, const int* in_sizes, int n_in,
                              void* d_out, int out_size)
{
    const float* x     = (const float*)d_in[0];
    const float* ln1_g = (const float*)d_in[1];
    const float* ln1_b = (const float*)d_in[2];
    const float* Wqkv  = (const float*)d_in[3];
    const float* bqkv  = (const float*)d_in[4];
    const float* Wproj = (const float*)d_in[5];
    const float* bproj = (const float*)d_in[6];
    const float* ln2_g = (const float*)d_in[7];
    const float* ln2_b = (const float*)d_in[8];
    const float* W1    = (const float*)d_in[9];
    const float* b1    = (const float*)d_in[10];
    const float* W2    = (const float*)d_in[11];
    const float* b2    = (const float*)d_in[12];
    float* out = (float*)d_out;

    fp16 *p_sc16, *p_p, *p_h, *p_kqv, *p_vT, *p_at, *p_h2, *p_mid;
    fp16 *WqT, *WpT, *W1T, *W2T;

    cudaGetSymbolAddress((void**)&p_sc16, g_sc16);
    cudaGetSymbolAddress((void**)&p_p,    g_p);
    cudaGetSymbolAddress((void**)&p_h,    g_h);
    cudaGetSymbolAddress((void**)&p_kqv,  g_kqv);
    cudaGetSymbolAddress((void**)&p_vT,   g_vT);
    cudaGetSymbolAddress((void**)&p_at,   g_at);
    cudaGetSymbolAddress((void**)&p_h2,   g_h2);
    cudaGetSymbolAddress((void**)&p_mid,  g_mid);
    cudaGetSymbolAddress((void**)&WqT,    g_WqkvT);
    cudaGetSymbolAddress((void**)&WpT,    g_WprjT);
    cudaGetSymbolAddress((void**)&W1T,    g_W1T);
    cudaGetSymbolAddress((void**)&W2T,    g_W2T);

    cudaFuncSetAttribute((const void*)gemm_h<2, 0>, cudaFuncAttributeMaxDynamicSharedMemorySize, SMEM_BYTES);
    cudaFuncSetAttribute((const void*)gemm_h<0, 0>, cudaFuncAttributeMaxDynamicSharedMemorySize, SMEM_BYTES);
    cudaFuncSetAttribute((const void*)gemm_h<3, 0>, cudaFuncAttributeMaxDynamicSharedMemorySize, SMEM_BYTES);
    cudaFuncSetAttribute((const void*)gemm_h<2, 1>, cudaFuncAttributeMaxDynamicSharedMemorySize, SMEM_BYTES);
    cudaFuncSetAttribute((const void*)gemm_h<2, 2>, cudaFuncAttributeMaxDynamicSharedMemorySize, SMEM_BYTES);

    const float inv_sqrt_T = 1.0f / sqrtf((float)T_);
    dim3 tb(32, 8);

    // All weight transposes in one launch
    transpose_all<<<12288, 256>>>(Wqkv, Wproj, W1, W2, WqT, WpT, W1T, W2T);

    // 1. LN1 (fp32 in) -> fp16 h
    ln_half<0><<<ROWS, 256>>>(x, ln1_g, ln1_b, p_h);

    // 2. QKV GEMM -> fp16 kqv
    gemm_h<2, 0><<<dim3(3 * D_ / 128, ROWS / 128, 1), 256, SMEM_BYTES>>>(
        p_h, WqT, bqkv, nullptr, p_kqv,
        D_, D_, D_, 3 * D_, 0, 0, 0, 1.f);

    // 3. V^T, batched
    transpose_h<<<dim3(D_ / 32, T_ / 32, B_), tb>>>(
        p_kqv + 2 * D_, p_vT, 3 * D_, T_,
        (long long)T_ * 3 * D_, (long long)D_ * T_);

    // 4. scores = q @ k^T * inv_sqrt_T (lower-tri blocks) -> fp16
    gemm_h<2, 1><<<dim3(T_ / 128, T_ / 128, B_), 256, SMEM_BYTES>>>(
        p_kqv + D_, p_kqv, nullptr, nullptr, p_sc16,
        D_, 3 * D_, 3 * D_, T_,
        (long long)T_ * 3 * D_, (long long)T_ * 3 * D_, (long long)T_ * T_, inv_sqrt_T);

    // 5. softmax -> fp16 probs
    softmax_h<<<dim3(T_, B_), 256>>>(p_sc16, p_p);

    // 6. attn @ v (K clipped, heavy CTAs first) -> fp16 at
    gemm_h<2, 2><<<dim3(D_ / 128, T_ / 128, B_), 256, SMEM_BYTES>>>(
        p_p, p_vT, nullptr, nullptr, p_at,
        T_, T_, T_, D_,
        (long long)T_ * T_, (long long)D_ * T_, (long long)T_ * D_, 1.f);

    // 7. proj -> fp16 (reuse g_h)
    gemm_h<2, 0><<<dim3(D_ / 128, ROWS / 128, 1), 256, SMEM_BYTES>>>(
        p_at, WpT, bproj, nullptr, p_h,
        D_, D_, D_, D_, 0, 0, 0, 1.f);

    // 8. LN2 (fp16 in) -> fp16 h2
    ln_half<1><<<ROWS, 256>>>(p_h, ln2_g, ln2_b, p_h2);

    // 9. MLP up + GELU -> fp16 mid
    gemm_h<3, 0><<<dim3(4 * D_ / 128, ROWS / 128, 1), 256, SMEM_BYTES>>>(
        p_h2, W1T, b1, nullptr, p_mid,
        D_, D_, D_, 4 * D_, 0, 0, 0, 1.f);

    // 10. MLP down -> fp32 out
    gemm_h<0, 0><<<dim3(D_ / 128, ROWS / 128, 1), 256, SMEM_BYTES>>>(
        p_mid, W2T, b2, out, nullptr,
        4 * D_, 4 * D_, 4 * D_, D_, 0, 0, 0, 1.f);
}

// round 17
// speedup vs baseline: 1.3162x; 1.0008x over previous
#include <cuda_runtime.h>
#include <cuda_fp16.h>
#include <math.h>
#include <stdint.h>

// Problem constants
#define B_ 4
#define T_ 2048
#define D_ 1024
#define ROWS (B_ * T_)        // 8192
#define EPS 1e-5f

typedef __half fp16;

// ---------------------------------------------------------------------------
// Scratch (allocation-free: __device__ globals)
// ---------------------------------------------------------------------------
__device__ fp16 g_sc16 [(size_t)B_ * T_ * T_];
__device__ fp16 g_p    [(size_t)B_ * T_ * T_];
__device__ fp16 g_h    [ROWS * D_];
__device__ fp16 g_kqv  [ROWS * 3 * D_];
__device__ fp16 g_vT   [(size_t)B_ * D_ * T_];
__device__ fp16 g_at   [ROWS * D_];
__device__ fp16 g_h2   [ROWS * D_];
__device__ fp16 g_mid  [ROWS * 4 * D_];
__device__ fp16 g_WqkvT[3 * D_ * D_];
__device__ fp16 g_WprjT[D_ * D_];
__device__ fp16 g_W1T  [4 * D_ * D_];
__device__ fp16 g_W2T  [D_ * 4 * D_];

// ---------------------------------------------------------------------------
// helpers
// ---------------------------------------------------------------------------
__device__ __forceinline__ uint32_t pack2h(fp16 a, fp16 b) {
    return (uint32_t)__half_as_ushort(a) | ((uint32_t)__half_as_ushort(b) << 16);
}
__device__ __forceinline__ void mma_fp16(float* d, const uint32_t* a, const uint32_t* b) {
    asm volatile(
        "mma.sync.aligned.m16n8k16.row.col.f32.f16.f16.f32 "
        "{%0,%1,%2,%3}, {%4,%5,%6,%7}, {%8,%9}, {%0,%1,%2,%3};"
        : "+f"(d[0]), "+f"(d[1]), "+f"(d[2]), "+f"(d[3])
        : "r"(a[0]), "r"(a[1]), "r"(a[2]), "r"(a[3]),
          "r"(b[0]), "r"(b[1]));
}
__device__ __forceinline__ uint32_t smem_u32(const void* p) {
    uint32_t a;
    asm("{ .reg .u64 t; cvta.to.shared.u64 t, %1; cvt.u32.u64 %0, t; }" : "=r"(a) : "l"(p));
    return a;
}
__device__ __forceinline__ void cp16(uint32_t dst, const void* src) {
    asm volatile("cp.async.cg.shared.global [%0], [%1], 16;" :: "r"(dst), "l"(src));
}
#define CP_COMMIT() asm volatile("cp.async.commit_group;" ::: "memory")
#define CP_WAIT2()  asm volatile("cp.async.wait_group 2;" ::: "memory")
#define CP_WAIT1()  asm volatile("cp.async.wait_group 1;" ::: "memory")
#define CP_WAIT0()  asm volatile("cp.async.wait_group 0;" ::: "memory")

#define LDSM_X4(d0, d1, d2, d3, addr) \
    asm volatile("ldmatrix.sync.aligned.m8n8.x4.shared.b16 {%0,%1,%2,%3}, [%4];" \
        : "=r"(d0), "=r"(d1), "=r"(d2), "=r"(d3) : "r"(addr))

// SMEM tile geometry: 128 rows x 32 fp16, row stride 40 elems (80B)
#define TILE_BYTES 10240
#define STAGE_BYTES (2 * TILE_BYTES)    // A + B tiles = 20480
#define NSTAGES 4
#define SMEM_BYTES (NSTAGES * STAGE_BYTES)   // 81920; x2 CTAs = 163840 <= 227KB

#define GRID_P 296   // 2 CTAs x 148 SMs

// ---------------------------------------------------------------------------
// Persistent 1-pass fp16 NT GEMM. 256 threads (8 warps of 64x32), 4-stage
// cp.async pipeline whose chunk stream runs ACROSS tile boundaries: next
// tile's loads overlap this tile's epilogue; only the first tile pays priming.
// C[M,N] = alpha*(A @ B^T) (+bias)
// EPI: 0=fp32 out, 2=fp16 out, 3=gelu+fp16 out
// CMODE: 0=dense (nx*ny tiles, bz=0)
//        1=causal lower-tri (per batch nx*(nx+1)/2 tiles, K fixed)
//        2=causal K clip (nx*ny per batch, heavy-by first)
// ---------------------------------------------------------------------------
template <int EPI, int CMODE>
__global__ void __launch_bounds__(256, 2) gemm_p(
    const fp16* __restrict__ A0, const fp16* __restrict__ B0,
    const float* __restrict__ bias,
    float* __restrict__ Cf, fp16* __restrict__ Ch,
    int K, int lda, int ldb, int ldc,
    long long sA, long long sB, long long sC, float alpha,
    int nx, int ny, int ntiles)
{
    if ((int)blockIdx.x >= ntiles) return;

    extern __shared__ fp16 smem[];
    const uint32_t sb = smem_u32(smem);

    const int tid = threadIdx.x;
    const int wid = tid >> 5, lane = tid & 31;
    const int wm = wid & 1, wn = wid >> 1;
    const int g = lane >> 2, tig = lane & 3;

    const uint32_t a_loff = (uint32_t)(((lane & 7) + ((lane >> 3) & 1) * 8) * 80 + ((lane >> 4) & 1) * 16);
    const uint32_t b_loff = (uint32_t)(((lane & 7) + ((lane >> 4) & 1) * 8) * 80 + ((lane >> 3) & 1) * 16);

    const int lrow = tid >> 1;
    const int lc   = (tid & 1) * 2;
    const uint32_t dbase = sb + lrow * 80 + lc * 16;

    const int stride = gridDim.x;

    // tile decode: t -> (m0, n0, bz, NC) and per-thread A/B load pointers
    auto decode = [&](int t, const fp16*& pA, const fp16*& pB,
                      int& NC_, int& m0_, int& n0_, int& bz_) {
        int bx_, by_;
        if (CMODE == 1) {
            const int per = nx * (nx + 1) / 2;
            bz_ = t / per;
            int ti = t - bz_ * per;
            int by = (int)((sqrtf(8.f * ti + 1.f) - 1.f) * 0.5f);
            while ((by + 1) * (by + 2) / 2 <= ti) by++;
            while (by * (by + 1) / 2 > ti) by--;
            bx_ = ti - by * (by + 1) / 2;
            by_ = by;
            NC_ = K >> 5;
        } else if (CMODE == 2) {
            const int per = nx * ny;
            bz_ = t / per;
            int r = t - bz_ * per;
            by_ = ny - 1 - r / nx;      // heavy tiles first
            bx_ = r % nx;
            int ke = (by_ + 1) * 128;
            NC_ = (ke < K ? ke : K) >> 5;
        } else {
            bz_ = 0;
            bx_ = t % nx;
            by_ = t / nx;
            NC_ = K >> 5;
        }
        m0_ = by_ * 128;
        n0_ = bx_ * 128;
        pA = A0 + sA * bz_ + (size_t)(m0_ + lrow) * lda + lc * 8;
        pB = B0 + sB * bz_ + (size_t)(n0_ + lrow) * ldb + lc * 8;
    };

    // --- prefetch stream state ---
    int pf_tile = blockIdx.x;
    const fp16 *pfA, *pfB;
    int pf_NC, pf_m0, pf_n0, pf_bz, pf_kc = 0;
    decode(pf_tile, pfA, pfB, pf_NC, pf_m0, pf_n0, pf_bz);
    int buf_issue = 0;
    int issued = 0, consumed = 0;

    auto pf_issue_one = [&]() {
        if (pf_tile >= ntiles) return;
        const uint32_t d0 = dbase + buf_issue * STAGE_BYTES;
        const int ko = pf_kc * 32;
        cp16(d0,                   pfA + ko);
        cp16(d0 + 16,              pfA + ko + 8);
        cp16(d0 + TILE_BYTES,      pfB + ko);
        cp16(d0 + TILE_BYTES + 16, pfB + ko + 8);
        CP_COMMIT();
        buf_issue = (buf_issue + 1) % NSTAGES;
        issued++;
        if (++pf_kc == pf_NC) {
            pf_kc = 0;
            pf_tile += stride;
            if (pf_tile < ntiles)
                decode(pf_tile, pfA, pfB, pf_NC, pf_m0, pf_n0, pf_bz);
        }
    };

    // prime 3 chunks of the stream
    pf_issue_one(); pf_issue_one(); pf_issue_one();

    int buf = 0;
    for (int tile = blockIdx.x; tile < ntiles; tile += stride) {
        const fp16 *duA, *duB;
        int NC, m0, n0, bz;
        decode(tile, duA, duB, NC, m0, n0, bz);

        float acc[4][4][4];
        #pragma unroll
        for (int i = 0; i < 4; i++)
            #pragma unroll
            for (int j = 0; j < 4; j++)
                #pragma unroll
                for (int r = 0; r < 4; r++) acc[i][j][r] = 0.f;

        for (int kc = 0; kc < NC; kc++) {
            const int out = issued - consumed;
            if (out >= 3)      { CP_WAIT2(); }
            else if (out == 2) { CP_WAIT1(); }
            else               { CP_WAIT0(); }
            __syncthreads();

            const uint32_t stage = sb + buf * STAGE_BYTES;
            const uint32_t aT = stage + (uint32_t)(wm * 64 * 80) + a_loff;
            const uint32_t bT = stage + TILE_BYTES + (uint32_t)(wn * 32 * 80) + b_loff;

            #pragma unroll
            for (int kk2 = 0; kk2 < 64; kk2 += 32) {
                uint32_t af[4][4], bf[4][2];
                #pragma unroll
                for (int mt = 0; mt < 4; mt++)
                    LDSM_X4(af[mt][0], af[mt][1], af[mt][2], af[mt][3], aT + mt * 1280 + kk2);
                #pragma unroll
                for (int p = 0; p < 2; p++)
                    LDSM_X4(bf[2*p][0], bf[2*p][1], bf[2*p+1][0], bf[2*p+1][1], bT + p * 1280 + kk2);
                #pragma unroll
                for (int mt = 0; mt < 4; mt++)
                    #pragma unroll
                    for (int nt = 0; nt < 4; nt++)
                        mma_fp16(acc[mt][nt], af[mt], bf[nt]);
            }

            consumed++;
            // refill: target buffer (buf+3)%4 was consumed 3 chunks ago (barrier since)
            pf_issue_one();
            buf = (buf + 1) % NSTAGES;
        }

        // epilogue (overlaps with already-issued prefetch of next tile)
        float* Cfp = (EPI == 0) ? (Cf + sC * bz) : nullptr;
        fp16*  Chp = (EPI != 0) ? (Ch + sC * bz) : nullptr;

        #pragma unroll
        for (int mt = 0; mt < 4; mt++) {
            #pragma unroll
            for (int nt = 0; nt < 4; nt++) {
                int m = m0 + wm * 64 + mt * 16 + g;
                int n = n0 + wn * 32 + nt * 8 + tig * 2;
                float2 bv = make_float2(0.f, 0.f);
                if (bias) bv = __ldg((const float2*)(bias + n));
                #pragma unroll
                for (int half_ = 0; half_ < 2; half_++) {
                    float vx = acc[mt][nt][half_ * 2 + 0] * alpha + bv.x;
                    float vy = acc[mt][nt][half_ * 2 + 1] * alpha + bv.y;
                    if (EPI == 3) {
                        const float c0 = 0.7978845608028654f, c1 = 0.044715f;
                        vx = 0.5f * vx * (1.f + tanhf(c0 * (vx + c1 * vx * vx * vx)));
                        vy = 0.5f * vy * (1.f + tanhf(c0 * (vy + c1 * vy * vy * vy)));
                    }
                    size_t off = (size_t)(m + half_ * 8) * ldc + n;
                    if (EPI == 0) {
                        *(float2*)(Cfp + off) = make_float2(vx, vy);
                    } else {
                        *(uint32_t*)(Chp + off) = pack2h(__float2half_rn(vx), __float2half_rn(vy));
                    }
                }
            }
        }
    }
}

// ---------------------------------------------------------------------------
// All 4 weight transposes in ONE launch (1D grid over 32x32 tiles)
// ---------------------------------------------------------------------------
__global__ void __launch_bounds__(256) transpose_all(
    const float* __restrict__ Wqkv, const float* __restrict__ Wproj,
    const float* __restrict__ W1, const float* __restrict__ W2,
    fp16* __restrict__ WqT, fp16* __restrict__ WpT,
    fp16* __restrict__ W1T, fp16* __restrict__ W2T)
{
    int t = blockIdx.x;
    const float* in; fp16* out;
    int ldi, ldo, bx, by;
    if (t < 3072)      { in = Wqkv;  out = WqT; ldi = 3072; ldo = 1024; t -= 0;    bx = t % 96;  by = t / 96;  }
    else if (t < 4096) { in = Wproj; out = WpT; ldi = 1024; ldo = 1024; t -= 3072; bx = t % 32;  by = t / 32;  }
    else if (t < 8192) { in = W1;    out = W1T; ldi = 4096; ldo = 1024; t -= 4096; bx = t % 128; by = t / 128; }
    else               { in = W2;    out = W2T; ldi = 1024; ldo = 4096; t -= 8192; bx = t % 32;  by = t / 32;  }

    __shared__ float tl[32][33];
    const int c0 = bx * 32, r0 = by * 32;
    const int x = threadIdx.x & 31, y = threadIdx.x >> 5;
    #pragma unroll
    for (int i = 0; i < 4; i++)
        tl[y + i * 8][x] = in[(size_t)(r0 + y + i * 8) * ldi + c0 + x];
    __syncthreads();
    #pragma unroll
    for (int i = 0; i < 4; i++)
        out[(size_t)(c0 + y + i * 8) * ldo + r0 + x] = __float2half_rn(tl[x][y + i * 8]);
}

// ---------------------------------------------------------------------------
// fp16 transpose (V -> V^T), batched
// ---------------------------------------------------------------------------
__global__ void __launch_bounds__(256) transpose_h(
    const fp16* __restrict__ in, fp16* __restrict__ out,
    int ldi, int ldo, long long sI, long long sO)
{
    __shared__ fp16 t[32][33];
    in  += sI * blockIdx.z;
    out += sO * blockIdx.z;
    const int c0 = blockIdx.x * 32, r0 = blockIdx.y * 32;
    const int x = threadIdx.x, y = threadIdx.y;
    #pragma unroll
    for (int i = 0; i < 4; i++)
        t[y + i * 8][x] = in[(size_t)(r0 + y + i * 8) * ldi + c0 + x];
    __syncthreads();
    #pragma unroll
    for (int i = 0; i < 4; i++)
        out[(size_t)(c0 + y + i * 8) * ldo + r0 + x] = t[x][y + i * 8];
}

// ---------------------------------------------------------------------------
// LayerNorm -> fp16 out. FIN=0: fp32 input, FIN=1: fp16 input.
// ---------------------------------------------------------------------------
template <int FIN>
__global__ void __launch_bounds__(256) ln_half(
    const void* __restrict__ xin, const float* __restrict__ gamma,
    const float* __restrict__ beta, fp16* __restrict__ o)
{
    __shared__ float4 xc[D_ / 4];
    const int row = blockIdx.x;

    float s = 0.f, ss = 0.f;
    {
        float4 v;
        if (FIN == 0) {
            v = __ldg((const float4*)xin + (size_t)row * (D_ / 4) + threadIdx.x);
        } else {
            uint2 pk = __ldg((const uint2*)xin + (size_t)row * (D_ / 4) + threadIdx.x);
            v.x = __half2float(__ushort_as_half((unsigned short)(pk.x & 0xFFFF)));
            v.y = __half2float(__ushort_as_half((unsigned short)(pk.x >> 16)));
            v.z = __half2float(__ushort_as_half((unsigned short)(pk.y & 0xFFFF)));
            v.w = __half2float(__ushort_as_half((unsigned short)(pk.y >> 16)));
        }
        xc[threadIdx.x] = v;
        s  = v.x + v.y + v.z + v.w;
        ss = v.x * v.x + v.y * v.y + v.z * v.z + v.w * v.w;
    }
    __shared__ float rs[8], rss[8];
    #pragma unroll
    for (int o2 = 16; o2 > 0; o2 >>= 1) {
        s  += __shfl_down_sync(0xffffffffu, s,  o2);
        ss += __shfl_down_sync(0xffffffffu, ss, o2);
    }
    int wid = threadIdx.x >> 5, lid = threadIdx.x & 31;
    if (lid == 0) { rs[wid] = s; rss[wid] = ss; }
    __syncthreads();
    __shared__ float s_mu, s_rstd;
    if (threadIdx.x == 0) {
        float ts = 0.f, tss = 0.f;
        #pragma unroll
        for (int i = 0; i < 8; i++) { ts += rs[i]; tss += rss[i]; }
        float mu = ts / D_;
        float var = tss / D_ - mu * mu;
        s_mu = mu;
        s_rstd = rsqrtf(var + EPS);
    }
    __syncthreads();
    float mu = s_mu, rstd = s_rstd;
    {
        int i = threadIdx.x;
        float4 v = xc[i];
        float4 gm = __ldg((const float4*)gamma + i);
        float4 bt = __ldg((const float4*)beta + i);
        fp16 h0 = __float2half_rn((v.x - mu) * rstd * gm.x + bt.x);
        fp16 h1 = __float2half_rn((v.y - mu) * rstd * gm.y + bt.y);
        fp16 h2 = __float2half_rn((v.z - mu) * rstd * gm.z + bt.z);
        fp16 h3 = __float2half_rn((v.w - mu) * rstd * gm.w + bt.w);
        uint2 pk = make_uint2(pack2h(h0, h1), pack2h(h2, h3));
        *(uint2*)(o + (size_t)row * D_ + i * 4) = pk;
    }
}

// ---------------------------------------------------------------------------
// Causal softmax: fp16 scores -> fp16 probs (fast exp, fill to block edge)
// ---------------------------------------------------------------------------
__global__ void __launch_bounds__(256) softmax_h(
    const fp16* __restrict__ sc, fp16* __restrict__ pr)
{
    __shared__ float cache[T_];
    const int t = blockIdx.x, b = blockIdx.y;
    const size_t ro = ((size_t)b * T_ + t) * T_;
    const fp16* row = sc + ro;
    const int n = t + 1;
    const int blk_end = ((t >> 7) + 1) << 7;

    __shared__ float red[8];
    __shared__ float s_bc;

    float mx = -INFINITY;
    for (int i = threadIdx.x; i < n; i += 256) {
        float v = __half2float(row[i]);
        cache[i] = v;
        mx = fmaxf(mx, v);
    }
    #pragma unroll
    for (int o = 16; o > 0; o >>= 1) mx = fmaxf(mx, __shfl_down_sync(0xffffffffu, mx, o));
    int wid = threadIdx.x >> 5, lid = threadIdx.x & 31;
    if (lid == 0) red[wid] = mx;
    __syncthreads();
    if (threadIdx.x == 0) {
        float m = red[0];
        #pragma unroll
        for (int i = 1; i < 8; i++) m = fmaxf(m, red[i]);
        s_bc = m;
    }
    __syncthreads();
    mx = s_bc;

    float sum = 0.f;
    for (int i = threadIdx.x; i < n; i += 256) {
        float e = __expf(cache[i] - mx);
        cache[i] = e;
        sum += e;
    }
    #pragma unroll
    for (int o = 16; o > 0; o >>= 1) sum += __shfl_down_sync(0xffffffffu, sum, o);
    if (lid == 0) red[wid] = sum;
    __syncthreads();
    if (threadIdx.x == 0) {
        float tot = 0.f;
        #pragma unroll
        for (int i = 0; i < 8; i++) tot += red[i];
        s_bc = 1.f / tot;
    }
    __syncthreads();
    float inv = s_bc;
    for (int i = threadIdx.x; i < n; i += 256)
        pr[ro + i] = __float2half_rn(cache[i] * inv);
    const fp16 z = __float2half(0.f);
    for (int i = n + threadIdx.x; i < blk_end; i += 256)
        pr[ro + i] = z;
}

// ---------------------------------------------------------------------------
// launch
// ---------------------------------------------------------------------------
extern "C" void kernel_launch(void* const* d_in, const int* in_sizes, int n_in,
                              void* d_out, int out_size)
{
    const float* x     = (const float*)d_in[0];
    const float* ln1_g = (const float*)d_in[1];
    const float* ln1_b = (const float*)d_in[2];
    const float* Wqkv  = (const float*)d_in[3];
    const float* bqkv  = (const float*)d_in[4];
    const float* Wproj = (const float*)d_in[5];
    const float* bproj = (const float*)d_in[6];
    const float* ln2_g = (const float*)d_in[7];
    const float* ln2_b = (const float*)d_in[8];
    const float* W1    = (const float*)d_in[9];
    const float* b1    = (const float*)d_in[10];
    const float* W2    = (const float*)d_in[11];
    const float* b2    = (const float*)d_in[12];
    float* out = (float*)d_out;

    fp16 *p_sc16, *p_p, *p_h, *p_kqv, *p_vT, *p_at, *p_h2, *p_mid;
    fp16 *WqT, *WpT, *W1T, *W2T;

    cudaGetSymbolAddress((void**)&p_sc16, g_sc16);
    cudaGetSymbolAddress((void**)&p_p,    g_p);
    cudaGetSymbolAddress((void**)&p_h,    g_h);
    cudaGetSymbolAddress((void**)&p_kqv,  g_kqv);
    cudaGetSymbolAddress((void**)&p_vT,   g_vT);
    cudaGetSymbolAddress((void**)&p_at,   g_at);
    cudaGetSymbolAddress((void**)&p_h2,   g_h2);
    cudaGetSymbolAddress((void**)&p_mid,  g_mid);
    cudaGetSymbolAddress((void**)&WqT,    g_WqkvT);
    cudaGetSymbolAddress((void**)&WpT,    g_WprjT);
    cudaGetSymbolAddress((void**)&W1T,    g_W1T);
    cudaGetSymbolAddress((void**)&W2T,    g_W2T);

    cudaFuncSetAttribute((const void*)gemm_p<2, 0>, cudaFuncAttributeMaxDynamicSharedMemorySize, SMEM_BYTES);
    cudaFuncSetAttribute((const void*)gemm_p<0, 0>, cudaFuncAttributeMaxDynamicSharedMemorySize, SMEM_BYTES);
    cudaFuncSetAttribute((const void*)gemm_p<3, 0>, cudaFuncAttributeMaxDynamicSharedMemorySize, SMEM_BYTES);
    cudaFuncSetAttribute((const void*)gemm_p<2, 1>, cudaFuncAttributeMaxDynamicSharedMemorySize, SMEM_BYTES);
    cudaFuncSetAttribute((const void*)gemm_p<2, 2>, cudaFuncAttributeMaxDynamicSharedMemorySize, SMEM_BYTES);

    const float inv_sqrt_T = 1.0f / sqrtf((float)T_);
    dim3 tb(32, 8);

    // All weight transposes in one launch
    transpose_all<<<12288, 256>>>(Wqkv, Wproj, W1, W2, WqT, WpT, W1T, W2T);

    // 1. LN1 (fp32 in) -> fp16 h
    ln_half<0><<<ROWS, 256>>>(x, ln1_g, ln1_b, p_h);

    // 2. QKV GEMM -> fp16 kqv  (nx=24, ny=64 -> 1536 tiles)
    gemm_p<2, 0><<<GRID_P, 256, SMEM_BYTES>>>(
        p_h, WqT, bqkv, nullptr, p_kqv,
        D_, D_, D_, 3 * D_, 0, 0, 0, 1.f,
        3 * D_ / 128, ROWS / 128, (3 * D_ / 128) * (ROWS / 128));

    // 3. V^T, batched
    transpose_h<<<dim3(D_ / 32, T_ / 32, B_), tb>>>(
        p_kqv + 2 * D_, p_vT, 3 * D_, T_,
        (long long)T_ * 3 * D_, (long long)D_ * T_);

    // 4. scores (lower-tri tiles only: 4 * 136 = 544)
    gemm_p<2, 1><<<GRID_P, 256, SMEM_BYTES>>>(
        p_kqv + D_, p_kqv, nullptr, nullptr, p_sc16,
        D_, 3 * D_, 3 * D_, T_,
        (long long)T_ * 3 * D_, (long long)T_ * 3 * D_, (long long)T_ * T_, inv_sqrt_T,
        T_ / 128, T_ / 128, B_ * (T_ / 128) * (T_ / 128 + 1) / 2);

    // 5. softmax -> fp16 probs
    softmax_h<<<dim3(T_, B_), 256>>>(p_sc16, p_p);

    // 6. attn @ v (K clipped, heavy first; 4 * 8 * 16 = 512 tiles)
    gemm_p<2, 2><<<GRID_P, 256, SMEM_BYTES>>>(
        p_p, p_vT, nullptr, nullptr, p_at,
        T_, T_, T_, D_,
        (long long)T_ * T_, (long long)D_ * T_, (long long)T_ * D_, 1.f,
        D_ / 128, T_ / 128, B_ * (D_ / 128) * (T_ / 128));

    // 7. proj -> fp16 (reuse g_h)
    gemm_p<2, 0><<<GRID_P, 256, SMEM_BYTES>>>(
        p_at, WpT, bproj, nullptr, p_h,
        D_, D_, D_, D_, 0, 0, 0, 1.f,
        D_ / 128, ROWS / 128, (D_ / 128) * (ROWS / 128));

    // 8. LN2 (fp16 in) -> fp16 h2
    ln_half<1><<<ROWS, 256>>>(p_h, ln2_g, ln2_b, p_h2);

    // 9. MLP up + GELU -> fp16 mid
    gemm_p<3, 0><<<GRID_P, 256, SMEM_BYTES>>>(
        p_h2, W1T, b1, nullptr, p_mid,
        D_, D_, D_, 4 * D_, 0, 0, 0, 1.f,
        4 * D_ / 128, ROWS / 128, (4 * D_ / 128) * (ROWS / 128));

    // 10. MLP down -> fp32 out
    gemm_p<0, 0><<<GRID_P, 256, SMEM_BYTES>>>(
        p_mid, W2T, b2, out, nullptr,
        4 * D_, 4 * D_, 4 * D_, D_, 0, 0, 0, 1.f,
        D_ / 128, ROWS / 128, (D_ / 128) * (ROWS / 128));
}